// round 16
// baseline (speedup 1.0000x reference)
#include <cuda_runtime.h>
#include <cuda_fp16.h>
#include <math.h>
#include <stdint.h>

#define Nn 100000
#define Ee 400000
#define RT 65536
#define EPSf 1e-5f
#define TAB_OUT ((size_t)RT*256)
#define GNN_OUT ((size_t)Nn*128)
#define CDIV(a,b) (((a)+(b)-1)/(b))
typedef __half h16;

// ---------- PTX helpers ----------
__device__ __forceinline__ uint32_t smem_u32(const void* p){
    uint32_t a; asm("{ .reg .u64 t; cvta.to.shared.u64 t, %1; cvt.u32.u64 %0, t; }":"=r"(a):"l"(p)); return a;
}
#define CP16(d,s)   asm volatile("cp.async.cg.shared.global [%0], [%1], 16;"::"r"((uint32_t)(d)),"l"(s))
#define CPC()       asm volatile("cp.async.commit_group;":::"memory")
#define CPW(n)      asm volatile("cp.async.wait_group %0;"::"n"(n):"memory")

__device__ __forceinline__ void ldsm4(uint32_t* r, uint32_t addr){
    asm volatile("ldmatrix.sync.aligned.m8n8.x4.shared.b16 {%0,%1,%2,%3}, [%4];"
        : "=r"(r[0]),"=r"(r[1]),"=r"(r[2]),"=r"(r[3]) : "r"(addr));
}
__device__ __forceinline__ void ldsm4t(uint32_t* r, uint32_t addr){
    asm volatile("ldmatrix.sync.aligned.m8n8.x4.trans.shared.b16 {%0,%1,%2,%3}, [%4];"
        : "=r"(r[0]),"=r"(r[1]),"=r"(r[2]),"=r"(r[3]) : "r"(addr));
}
__device__ __forceinline__ void mma16816(float* d, const uint32_t* a, uint32_t b0, uint32_t b1){
    asm volatile("mma.sync.aligned.m16n8k16.row.col.f32.f16.f16.f32 "
        "{%0,%1,%2,%3},{%4,%5,%6,%7},{%8,%9},{%0,%1,%2,%3};"
        : "+f"(d[0]),"+f"(d[1]),"+f"(d[2]),"+f"(d[3])
        : "r"(a[0]),"r"(a[1]),"r"(a[2]),"r"(a[3]),"r"(b0),"r"(b1));
}

// ---------- scratch ----------
__device__ __align__(256) h16  g_qkvh[(size_t)RT*768];
__device__ __align__(256) h16  g_xth[(size_t)RT*256];
__device__ __align__(256) h16  g_aoh[(size_t)RT*256];
__device__ __align__(256) h16  g_h1h[(size_t)RT*256];
__device__ __align__(256) h16  g_f1h[(size_t)RT*1024];
__device__ __align__(256) h16 g_wq_h[768*256];
__device__ __align__(256) h16 g_wo_h[256*256];
__device__ __align__(256) h16 g_w1_h[1024*256];
__device__ __align__(256) h16 g_w2_h[256*1024];
__device__ __align__(256) h16 g_wnode[256*128];
__device__ __align__(256) h16 g_wedge[128*128];
__device__ __align__(256) h16 g_wstk_h[384*640];
__device__ float g_bpre[128], g_bias2[128];
__device__ float g_bz[256];     // stays zero
__device__ __align__(256) h16 g_xgh[(size_t)Nn*128];
__device__ __align__(256) h16 g_p12[(size_t)Nn*256];
__device__ __align__(256) h16 g_eah[(size_t)Ee*128];
__device__ __align__(256) h16 g_Hh[(size_t)Ee*128];
__device__ __align__(256) h16 g_aggh[(size_t)Nn*640];
__device__ __align__(256) h16 g_Yh[(size_t)Nn*128];
__device__ float g_amp[Nn], g_att[Nn];
__device__ int g_deg[Nn], g_rowstart[Nn+1], g_cursor[Nn], g_eid[Ee];
__device__ float g_bnsum[128], g_bnsq[128];

// ---------- converters ----------
__global__ void k_r16(const float* __restrict__ s, h16* __restrict__ d, size_t n){
    for (size_t i=blockIdx.x*(size_t)blockDim.x+threadIdx.x; i<n; i+=(size_t)gridDim.x*blockDim.x)
        d[i]=__float2half(s[i]);
}
// x_gnn convert + zero init (deg/cursor/bn)
__global__ void k_init_gnn(const float* __restrict__ s){
    size_t gid=blockIdx.x*(size_t)blockDim.x+threadIdx.x;
    if (gid<Nn){ g_deg[gid]=0; g_cursor[gid]=0; }
    if (gid<128){ g_bnsum[gid]=0.f; g_bnsq[gid]=0.f; }
    for (size_t i=gid; i<(size_t)Nn*128; i+=(size_t)gridDim.x*blockDim.x)
        g_xgh[i]=__float2half(s[i]);
}
__global__ void k_ea16(const float4* __restrict__ s, float4* __restrict__ out, uint2* __restrict__ d, int n4){
    for (int i=blockIdx.x*blockDim.x+threadIdx.x; i<n4; i+=gridDim.x*blockDim.x){
        float4 v=s[i]; out[i]=v;
        __half2 p0=__floats2half2_rn(v.x,v.y), p1=__floats2half2_rn(v.z,v.w);
        uint2 u; u.x=*(uint32_t*)&p0; u.y=*(uint32_t*)&p1;
        d[i]=u;
    }
}

// ===================================================================
// fp16 single-term GEMM (N-tiled): C = A16 @ W16^T + bias
// EPI 1: relu+fp16; 2: fp16+bias
// ===================================================================
#define STGS 4
#define STAGE_BYTES 16384
#define GEMM_SMEM (STGS*STAGE_BYTES)

template<int EPI>
__global__ void __launch_bounds__(256) k_mm(
    const h16* __restrict__ A, const h16* __restrict__ Wh,
    const float* __restrict__ bias, h16* __restrict__ Ch,
    int M, int Ntot, int K)
{
    extern __shared__ __align__(128) char smem[];
    uint32_t sb = smem_u32(smem);
    int tid=threadIdx.x, lane=tid&31, wid=tid>>5;
    int m0=blockIdx.y*128, n0=blockIdx.x*128;
    int wm=(wid&1)*64, wn=(wid>>1)*32;

    int lr=tid>>1, lc=tid&1;
    uint32_t wb = ((uint32_t)(lr>>3)<<9) + ((uint32_t)(lr&7)<<4);
    uint32_t wd0 = wb + ((uint32_t)(2*lc)<<7);
    uint32_t wd1 = wb + ((uint32_t)(2*lc+1)<<7);
    int ar=min(m0+lr, M-1);
    const h16 *pA = A + (size_t)ar*K + lc*16;
    const h16 *pWh= Wh+ (size_t)(n0+lr)*K + lc*16;
    int nst=K>>5;

#define LDST(st,k0) do{ uint32_t _o=sb+(uint32_t)(st)*STAGE_BYTES; int _k=(k0); \
    CP16(_o+wd0, pA+_k);        CP16(_o+wd1, pA+_k+8); \
    CP16(_o+8192+wd0, pWh+_k);  CP16(_o+8192+wd1, pWh+_k+8); \
    CPC(); }while(0)

    int l7=lane&7, t8=(lane>>3)&1, t16=lane>>4;
    uint32_t fb = ((uint32_t)l7<<4) + ((uint32_t)t16<<7);
    uint32_t bA[4], bB[2];
    #pragma unroll
    for (int m=0;m<4;m++) bA[m] = ((uint32_t)((wm>>3)+2*m+t8)<<9) + fb;
    #pragma unroll
    for (int g=0;g<2;g++) bB[g] = 8192u + ((uint32_t)((wn>>3)+2*g+t8)<<9) + fb;

    float acc[4][4][4];
    #pragma unroll
    for (int m=0;m<4;m++)
        #pragma unroll
        for (int nf=0;nf<4;nf++)
            #pragma unroll
            for (int q=0;q<4;q++) acc[m][nf][q]=0.f;

    LDST(0,0);
    if (nst>1) LDST(1,32);
    if (nst>2) LDST(2,64);

    for (int s=0;s<nst;s++){
        if (s < nst-2) CPW(2); else if (s==nst-2) CPW(1); else CPW(0);
        __syncthreads();
        if (s+3<nst) LDST((s+3)&3, (s+3)*32);
        uint32_t st = sb + (uint32_t)(s&3)*STAGE_BYTES;
        #pragma unroll
        for (int ks=0;ks<2;ks++){
            uint32_t ko = (uint32_t)ks<<8;
            uint32_t Af[4][4], Bh[2][4];
            #pragma unroll
            for (int m=0;m<4;m++) ldsm4(Af[m], st + bA[m] + ko);
            #pragma unroll
            for (int g=0;g<2;g++) ldsm4(Bh[g], st + bB[g] + ko);
            #pragma unroll
            for (int m=0;m<4;m++)
                #pragma unroll
                for (int nf=0;nf<4;nf++){
                    int g=nf>>1,o=nf&1;
                    mma16816(acc[m][nf],Af[m],Bh[g][o],Bh[g][2+o]);
                }
        }
    }
#undef LDST

    int lq=lane>>2, lrm=lane&3;
    #pragma unroll
    for (int m=0;m<4;m++)
        #pragma unroll
        for (int nf=0;nf<4;nf++){
            int gm=m0+wm+m*16+lq;
            int gn=n0+wn+nf*8+lrm*2;
            float b0=bias[gn], b1=bias[gn+1];
            float* a4=acc[m][nf];
            #pragma unroll
            for (int hr=0;hr<2;hr++){
                int r=gm+hr*8;
                if (r<M){
                    float v0=a4[hr*2+0]+b0, v1=a4[hr*2+1]+b1;
                    if (EPI==1){ v0=fmaxf(v0,0.f); v1=fmaxf(v1,0.f); }
                    __half2 p=__floats2half2_rn(v0,v1);
                    *(uint32_t*)(Ch+(size_t)r*Ntot+gn)=*(uint32_t*)&p;
                }
            }
        }
}

// ===================================================================
// fused full-row GEMM + LayerNorm, single-term W, fp16 residual.
// FLN 1: h1 = LN1(res16 + A@W + b) -> g_h1h;  FLN 2: LNt(LN2(...)) -> fp32
// ===================================================================
#define FST 24576
#define FSM (4*FST)

template<int FLN>
__global__ void __launch_bounds__(512) k_mmln(
    const h16* __restrict__ A, const h16* __restrict__ Wh,
    const float* __restrict__ bias, const h16* __restrict__ res,
    const float* __restrict__ g1, const float* __restrict__ b1,
    const float* __restrict__ g2, const float* __restrict__ b2,
    float* __restrict__ outf, int K)
{
    extern __shared__ __align__(128) char smem[];
    uint32_t sb = smem_u32(smem);
    int tid=threadIdx.x, lane=tid&31, wid=tid>>5;
    int m0=blockIdx.x*128;
    int wm=(wid&1)*64, wn=(wid>>1)*32;

    int rowA=tid>>2, cA=tid&3;
    const h16 *pA  = A  + (size_t)(m0+rowA)*K + cA*8;
    const h16 *pW0h= Wh + (size_t)rowA*K + cA*8;
    const h16 *pW1h= Wh + (size_t)(rowA+128)*K + cA*8;
    uint32_t dA  = ((uint32_t)(rowA>>3)<<9)+((uint32_t)(rowA&7)<<4)+((uint32_t)cA<<7);
    uint32_t dW0 = 8192u + dA;
    int nst=K>>5;

#define LDF(st,k0) do{ uint32_t _o=sb+(uint32_t)(st)*FST; int _k=(k0); \
    CP16(_o+dA, pA+_k); \
    CP16(_o+dW0, pW0h+_k); CP16(_o+dW0+8192, pW1h+_k); \
    CPC(); }while(0)

    int l7=lane&7, t8=(lane>>3)&1, t16=lane>>4;
    uint32_t fb = ((uint32_t)l7<<4) + ((uint32_t)t16<<7);
    uint32_t bA[4], bB[2];
    #pragma unroll
    for (int m=0;m<4;m++) bA[m] = ((uint32_t)((wm>>3)+2*m+t8)<<9) + fb;
    #pragma unroll
    for (int g=0;g<2;g++) bB[g] = 8192u + ((uint32_t)((wn>>3)+2*g+t8)<<9) + fb;

    float acc[4][4][4];
    #pragma unroll
    for (int m=0;m<4;m++)
        #pragma unroll
        for (int nf=0;nf<4;nf++)
            #pragma unroll
            for (int q=0;q<4;q++) acc[m][nf][q]=0.f;

    LDF(0,0); LDF(1,32); LDF(2,64);

    for (int s=0;s<nst;s++){
        if (s < nst-2) CPW(2); else if (s==nst-2) CPW(1); else CPW(0);
        __syncthreads();
        if (s+3<nst) LDF((s+3)&3, (s+3)*32);
        uint32_t st = sb + (uint32_t)(s&3)*FST;
        #pragma unroll
        for (int ks=0;ks<2;ks++){
            uint32_t ko = (uint32_t)ks<<8;
            uint32_t Af[4][4], Bh[2][4];
            #pragma unroll
            for (int m=0;m<4;m++) ldsm4(Af[m], st + bA[m] + ko);
            #pragma unroll
            for (int g=0;g<2;g++) ldsm4(Bh[g], st + bB[g] + ko);
            #pragma unroll
            for (int m=0;m<4;m++)
                #pragma unroll
                for (int nf=0;nf<4;nf++){
                    int g=nf>>1,o=nf&1;
                    mma16816(acc[m][nf],Af[m],Bh[g][o],Bh[g][2+o]);
                }
        }
    }
#undef LDF

    __syncthreads();
    float* red = (float*)smem;
    int lq=lane>>2, lrm=lane&3, nw=wid>>1;

    #pragma unroll
    for (int m=0;m<4;m++)
        #pragma unroll
        for (int nf=0;nf<4;nf++){
            int gn=wn+nf*8+lrm*2;
            float b0=bias[gn], b1v=bias[gn+1];
            #pragma unroll
            for (int hr=0;hr<2;hr++){
                int r=m0+wm+m*16+lq+hr*8;
                uint32_t xr=*(const uint32_t*)(res+(size_t)r*256+gn);
                __half2 hx=*(__half2*)&xr;
                acc[m][nf][2*hr]  += b0 + __low2float(hx);
                acc[m][nf][2*hr+1]+= b1v+ __high2float(hx);
            }
        }
    #pragma unroll
    for (int m=0;m<4;m++)
        #pragma unroll
        for (int hr=0;hr<2;hr++){
            float ps=0.f, pq=0.f;
            #pragma unroll
            for (int nf=0;nf<4;nf++){
                float a0=acc[m][nf][2*hr], a1=acc[m][nf][2*hr+1];
                ps+=a0+a1; pq+=a0*a0+a1*a1;
            }
            ps+=__shfl_xor_sync(~0u,ps,1); ps+=__shfl_xor_sync(~0u,ps,2);
            pq+=__shfl_xor_sync(~0u,pq,1); pq+=__shfl_xor_sync(~0u,pq,2);
            if (lrm==0){ int rl=wm+m*16+lq+hr*8; red[rl*8+nw]=ps; red[1024+rl*8+nw]=pq; }
        }
    __syncthreads();
    float mu[4][2], inv[4][2];
    #pragma unroll
    for (int m=0;m<4;m++)
        #pragma unroll
        for (int hr=0;hr<2;hr++){
            int rl=wm+m*16+lq+hr*8;
            float s=0.f,q=0.f;
            #pragma unroll
            for (int k=0;k<8;k++){ s+=red[rl*8+k]; q+=red[1024+rl*8+k]; }
            float m1=s*(1.f/256.f);
            mu[m][hr]=m1; inv[m][hr]=rsqrtf(q*(1.f/256.f)-m1*m1+EPSf);
        }
    #pragma unroll
    for (int m=0;m<4;m++)
        #pragma unroll
        for (int nf=0;nf<4;nf++){
            int gn=wn+nf*8+lrm*2;
            float gg0=g1[gn], gg1=g1[gn+1], bb0=b1[gn], bb1=b1[gn+1];
            #pragma unroll
            for (int hr=0;hr<2;hr++){
                acc[m][nf][2*hr]  = gg0*(acc[m][nf][2*hr]  -mu[m][hr])*inv[m][hr]+bb0;
                acc[m][nf][2*hr+1]= gg1*(acc[m][nf][2*hr+1]-mu[m][hr])*inv[m][hr]+bb1;
            }
        }
    if (FLN==1){
        #pragma unroll
        for (int m=0;m<4;m++)
            #pragma unroll
            for (int nf=0;nf<4;nf++){
                int gn=wn+nf*8+lrm*2;
                #pragma unroll
                for (int hr=0;hr<2;hr++){
                    int r=m0+wm+m*16+lq+hr*8;
                    __half2 p=__floats2half2_rn(acc[m][nf][2*hr],acc[m][nf][2*hr+1]);
                    *(uint32_t*)(g_h1h+(size_t)r*256+gn)=*(uint32_t*)&p;
                }
            }
    } else {
        __syncthreads();
        #pragma unroll
        for (int m=0;m<4;m++)
            #pragma unroll
            for (int hr=0;hr<2;hr++){
                float ps=0.f,pq=0.f;
                #pragma unroll
                for (int nf=0;nf<4;nf++){
                    float a0=acc[m][nf][2*hr], a1=acc[m][nf][2*hr+1];
                    ps+=a0+a1; pq+=a0*a0+a1*a1;
                }
                ps+=__shfl_xor_sync(~0u,ps,1); ps+=__shfl_xor_sync(~0u,ps,2);
                pq+=__shfl_xor_sync(~0u,pq,1); pq+=__shfl_xor_sync(~0u,pq,2);
                if (lrm==0){ int rl=wm+m*16+lq+hr*8; red[rl*8+nw]=ps; red[1024+rl*8+nw]=pq; }
            }
        __syncthreads();
        #pragma unroll
        for (int m=0;m<4;m++)
            #pragma unroll
            for (int hr=0;hr<2;hr++){
                int rl=wm+m*16+lq+hr*8;
                float s=0.f,q=0.f;
                #pragma unroll
                for (int k=0;k<8;k++){ s+=red[rl*8+k]; q+=red[1024+rl*8+k]; }
                float m1=s*(1.f/256.f);
                mu[m][hr]=m1; inv[m][hr]=rsqrtf(q*(1.f/256.f)-m1*m1+EPSf);
            }
        #pragma unroll
        for (int m=0;m<4;m++)
            #pragma unroll
            for (int nf=0;nf<4;nf++){
                int gn=wn+nf*8+lrm*2;
                float gg0=g2[gn], gg1=g2[gn+1], bb0=b2[gn], bb1=b2[gn+1];
                #pragma unroll
                for (int hr=0;hr<2;hr++){
                    int r=m0+wm+m*16+lq+hr*8;
                    float v0=gg0*(acc[m][nf][2*hr]  -mu[m][hr])*inv[m][hr]+bb0;
                    float v1=gg1*(acc[m][nf][2*hr+1]-mu[m][hr])*inv[m][hr]+bb1;
                    *(float2*)(outf+(size_t)r*256+gn)=make_float2(v0,v1);
                }
            }
    }
}

// ===================================================================
// edge GEMM, persistent-W multi-tile:
// W_edge (32KB) loaded once; PTILES M-tiles of 128 edges streamed.
// H[r] = ea[eid[r]]@Wedge^T + bpre + P2[src]   (P1 shift applied in k_agg)
// smem: W@0 (4x8KB sub-blocks), A stages @32768 + st*8192 (4 stages)
// ===================================================================
#define PTILES 8
#define NTILES_TOT (Ee/128)
#define PRE_SMEM 65536

__global__ void __launch_bounds__(256) k_mm_pre2(const int* __restrict__ ei)
{
    extern __shared__ __align__(128) char smem[];
    uint32_t sb = smem_u32(smem);
    uint32_t sbA = sb + 32768;
    int tid=threadIdx.x, lane=tid&31, wid=tid>>5;
    int wm=(wid&1)*64, wn=(wid>>1)*32;
    int tile0 = blockIdx.x*PTILES;
    int tiles = min(PTILES, NTILES_TOT - tile0);

    int lr=tid>>1, lc=tid&1;
    uint32_t wb = ((uint32_t)(lr>>3)<<9) + ((uint32_t)(lr&7)<<4);
    uint32_t wd0 = wb + ((uint32_t)(2*lc)<<7);
    uint32_t wd1 = wb + ((uint32_t)(2*lc+1)<<7);

    // load W once (4 K-sub-blocks of 8KB)
    {
        const h16 *pW = g_wedge + (size_t)lr*128 + lc*16;
        #pragma unroll
        for (int kg=0;kg<4;kg++){
            CP16(sb + (uint32_t)kg*8192 + wd0, pW + kg*32);
            CP16(sb + (uint32_t)kg*8192 + wd1, pW + kg*32 + 8);
        }
        CPC();
    }

#define LDA(G) do{ int _G=(G); int _tt=_G>>2, _kc=_G&3; \
    int _e = g_eid[(tile0+_tt)*128 + lr]; \
    const h16* _pa = g_eah + (size_t)_e*128 + lc*16 + _kc*32; \
    uint32_t _o = sbA + (uint32_t)(_G&3)*8192; \
    CP16(_o+wd0, _pa); CP16(_o+wd1, _pa+8); \
    CPC(); }while(0)

    int NG = tiles*4;
    LDA(0); LDA(1); LDA(2);
    CPW(3);            // W group done (3 A groups may be pending)
    __syncthreads();

    int l7=lane&7, t8=(lane>>3)&1, t16=lane>>4;
    uint32_t fb = ((uint32_t)l7<<4) + ((uint32_t)t16<<7);
    uint32_t bA[4], bBrel[2];
    #pragma unroll
    for (int m=0;m<4;m++) bA[m] = ((uint32_t)((wm>>3)+2*m+t8)<<9) + fb;
    #pragma unroll
    for (int g=0;g<2;g++) bBrel[g] = ((uint32_t)((wn>>3)+2*g+t8)<<9) + fb;

    int lq=lane>>2, lrm=lane&3;
    float acc[4][4][4];
    #pragma unroll
    for (int m=0;m<4;m++)
        #pragma unroll
        for (int nf=0;nf<4;nf++)
            #pragma unroll
            for (int q=0;q<4;q++) acc[m][nf][q]=0.f;

    for (int G=0; G<NG; G++){
        if (G < NG-2) CPW(2); else if (G==NG-2) CPW(1); else CPW(0);
        __syncthreads();
        if (G+3<NG) LDA(G+3);
        uint32_t stA = sbA + (uint32_t)(G&3)*8192;
        uint32_t stW = sb  + (uint32_t)(G&3)*8192;
        #pragma unroll
        for (int ks=0;ks<2;ks++){
            uint32_t ko = (uint32_t)ks<<8;
            uint32_t Af[4][4], Bh[2][4];
            #pragma unroll
            for (int m=0;m<4;m++) ldsm4(Af[m], stA + bA[m] + ko);
            #pragma unroll
            for (int g=0;g<2;g++) ldsm4(Bh[g], stW + bBrel[g] + ko);
            #pragma unroll
            for (int m=0;m<4;m++)
                #pragma unroll
                for (int nf=0;nf<4;nf++){
                    int g=nf>>1,o=nf&1;
                    mma16816(acc[m][nf],Af[m],Bh[g][o],Bh[g][2+o]);
                }
        }
        if ((G&3)==3){
            int m0=(tile0 + (G>>2))*128;
            #pragma unroll
            for (int m=0;m<4;m++)
                #pragma unroll
                for (int hr=0;hr<2;hr++){
                    int r=m0+wm+m*16+lq+hr*8;
                    int e2=g_eid[r];
                    int vs=ei[e2];
                    const h16* p2=g_p12+(size_t)vs*256+128;
                    #pragma unroll
                    for (int nf=0;nf<4;nf++){
                        int gn=wn+nf*8+lrm*2;
                        uint32_t u2=*(const uint32_t*)(p2+gn);
                        __half2 h2v=*(__half2*)&u2;
                        float v0=acc[m][nf][2*hr]  +g_bpre[gn]  +__low2float(h2v);
                        float v1=acc[m][nf][2*hr+1]+g_bpre[gn+1]+__high2float(h2v);
                        __half2 p=__floats2half2_rn(v0,v1);
                        *(uint32_t*)(g_Hh+(size_t)r*128+gn)=*(uint32_t*)&p;
                    }
                }
            #pragma unroll
            for (int m=0;m<4;m++)
                #pragma unroll
                for (int nf=0;nf<4;nf++)
                    #pragma unroll
                    for (int q=0;q<4;q++) acc[m][nf][q]=0.f;
        }
    }
#undef LDA
}

// ===================================================================
// post GEMM two-pass (A loaded once in pass B), fused BN stats, Y fp16
// ===================================================================
#define QSTG 24576
#define POST_SMEM (4*QSTG)

__global__ void __launch_bounds__(256) k_post3()
{
    extern __shared__ __align__(128) char smem[];
    uint32_t sb = smem_u32(smem);
    int tid=threadIdx.x, lane=tid&31, wid=tid>>5;
    int m0=blockIdx.x*128;
    int wm=(wid&1)*64, wn=(wid>>1)*32;

    int lr=tid>>1, lc=tid&1;
    uint32_t wb = ((uint32_t)(lr>>3)<<9) + ((uint32_t)(lr&7)<<4);
    uint32_t wd0 = wb + ((uint32_t)(2*lc)<<7);
    uint32_t wd1 = wb + ((uint32_t)(2*lc+1)<<7);
    int ar=min(m0+lr, Nn-1);
    const h16 *pA = g_aggh + (size_t)ar*640 + lc*16;
    const int nst=36;

#define LDQ(st,c) do{ uint32_t _o=sb+(uint32_t)(st)*QSTG; \
    int _k = ((c)<20)? (c)*32 : 128+((c)-20)*32; \
    CP16(_o+wd0, pA+_k); CP16(_o+wd1, pA+_k+8); \
    if ((c)<20){ \
        const h16* _w=g_wstk_h+(size_t)lr*640+_k+lc*16; \
        CP16(_o+8192+wd0,_w); CP16(_o+8192+wd1,_w+8); \
    } else { \
        const h16* _w1=g_wstk_h+(size_t)(128+lr)*640+_k+lc*16; \
        const h16* _w2=g_wstk_h+(size_t)(256+lr)*640+_k+lc*16; \
        CP16(_o+8192+wd0,_w1);  CP16(_o+8192+wd1,_w1+8); \
        CP16(_o+16384+wd0,_w2); CP16(_o+16384+wd1,_w2+8); \
    } \
    CPC(); }while(0)

    int l7=lane&7, t8=(lane>>3)&1, t16=lane>>4;
    uint32_t fb = ((uint32_t)l7<<4) + ((uint32_t)t16<<7);
    uint32_t bA[4], bB[2];
    #pragma unroll
    for (int m=0;m<4;m++) bA[m] = ((uint32_t)((wm>>3)+2*m+t8)<<9) + fb;
    #pragma unroll
    for (int g=0;g<2;g++) bB[g] = 8192u + ((uint32_t)((wn>>3)+2*g+t8)<<9) + fb;

    int lq=lane>>2, lrm=lane&3;
    float ampv[4][2], attv[4][2];
    #pragma unroll
    for (int m=0;m<4;m++)
        #pragma unroll
        for (int hr=0;hr<2;hr++){
            int r=min(m0+wm+m*16+lq+hr*8, Nn-1);
            ampv[m][hr]=g_amp[r]; attv[m][hr]=g_att[r];
        }

    float accM[4][4][4], accT1[4][4][4], accT2[4][4][4];
    #pragma unroll
    for (int m=0;m<4;m++)
        #pragma unroll
        for (int nf=0;nf<4;nf++)
            #pragma unroll
            for (int q=0;q<4;q++){ accM[m][nf][q]=0.f; accT1[m][nf][q]=0.f; accT2[m][nf][q]=0.f; }

    LDQ(0,0); LDQ(1,1); LDQ(2,2);

    for (int s=0;s<nst;s++){
        if (s < nst-2) CPW(2); else if (s==nst-2) CPW(1); else CPW(0);
        __syncthreads();
        if (s+3<nst) LDQ((s+3)&3, s+3);
        uint32_t st = sb + (uint32_t)(s&3)*QSTG;
        if (s<20){
            #pragma unroll
            for (int ks=0;ks<2;ks++){
                uint32_t ko = (uint32_t)ks<<8;
                uint32_t Af[4][4], B1[2][4];
                #pragma unroll
                for (int m=0;m<4;m++) ldsm4(Af[m], st + bA[m] + ko);
                #pragma unroll
                for (int g=0;g<2;g++) ldsm4(B1[g], st + bB[g] + ko);
                #pragma unroll
                for (int m=0;m<4;m++)
                    #pragma unroll
                    for (int nf=0;nf<4;nf++){
                        int g=nf>>1,o=nf&1;
                        mma16816(accM[m][nf],Af[m],B1[g][o],B1[g][2+o]);
                    }
            }
        } else {
            #pragma unroll
            for (int ks=0;ks<2;ks++){
                uint32_t ko = (uint32_t)ks<<8;
                uint32_t Af[4][4], B1[2][4], B2[2][4];
                #pragma unroll
                for (int m=0;m<4;m++) ldsm4(Af[m], st + bA[m] + ko);
                #pragma unroll
                for (int g=0;g<2;g++){ ldsm4(B1[g], st + bB[g] + ko); ldsm4(B2[g], st + bB[g] + 8192 + ko); }
                #pragma unroll
                for (int m=0;m<4;m++)
                    #pragma unroll
                    for (int nf=0;nf<4;nf++){
                        int g=nf>>1,o=nf&1;
                        mma16816(accT1[m][nf],Af[m],B1[g][o],B1[g][2+o]);
                        mma16816(accT2[m][nf],Af[m],B2[g][o],B2[g][2+o]);
                    }
            }
        }
    }
#undef LDQ

    #pragma unroll
    for (int m=0;m<4;m++)
        #pragma unroll
        for (int nf=0;nf<4;nf++)
            #pragma unroll
            for (int q=0;q<4;q++)
                accM[m][nf][q] += ampv[m][q>>1]*accT1[m][nf][q] + attv[m][q>>1]*accT2[m][nf][q];

    __syncthreads();
    float* redS=(float*)smem;
    if (tid<256) redS[tid]=0.f;
    __syncthreads();

    #pragma unroll
    for (int m=0;m<4;m++)
        #pragma unroll
        for (int nf=0;nf<4;nf++){
            int gm=m0+wm+m*16+lq;
            int gn=wn+nf*8+lrm*2;
            float b0=g_bias2[gn], b1=g_bias2[gn+1];
            float s0=0.f,q0=0.f,s1=0.f,q1=0.f;
            float* a4=accM[m][nf];
            #pragma unroll
            for (int hr=0;hr<2;hr++){
                int r=gm+hr*8;
                if (r<Nn){
                    float v0=a4[hr*2+0]+b0, v1=a4[hr*2+1]+b1;
                    __half2 p=__floats2half2_rn(v0,v1);
                    *(uint32_t*)(g_Yh+(size_t)r*128+gn)=*(uint32_t*)&p;
                    s0+=v0; q0+=v0*v0; s1+=v1; q1+=v1*v1;
                }
            }
            atomicAdd(&redS[gn], s0);    atomicAdd(&redS[128+gn], q0);
            atomicAdd(&redS[gn+1], s1);  atomicAdd(&redS[128+gn+1], q1);
        }
    __syncthreads();
    if (tid<128){ atomicAdd(&g_bnsum[tid], redS[tid]); atomicAdd(&g_bnsq[tid], redS[128+tid]); }
}

// ---------- tensor-core attention ----------
__global__ void __launch_bounds__(128) k_attn(const h16* __restrict__ qkv){
    __shared__ h16 qs[64*40], ks[64*40], vs[64*40];
    int bh=blockIdx.x, b=bh>>3, h=bh&7;
    int tid=threadIdx.x, lane=tid&31, wid=tid>>5;
    const h16* base = qkv + (size_t)b*64*768 + h*32;
    for (int i=tid;i<256;i+=128){
        int r=i>>2, c=(i&3)*8;
        *(uint4*)(qs+r*40+c)=*(const uint4*)(base+(size_t)r*768+c);
        *(uint4*)(ks+r*40+c)=*(const uint4*)(base+(size_t)r*768+256+c);
        *(uint4*)(vs+r*40+c)=*(const uint4*)(base+(size_t)r*768+512+c);
    }
    __syncthreads();
    uint32_t qb=smem_u32(qs), kb=smem_u32(ks), vb=smem_u32(vs);
    int m0=wid*16;
    float s[8][4];
    #pragma unroll
    for (int nt=0;nt<8;nt++)
        #pragma unroll
        for (int q=0;q<4;q++) s[nt][q]=0.f;

    #pragma unroll
    for (int kc=0;kc<2;kc++){
        uint32_t a[4];
        ldsm4(a, qb + (uint32_t)(m0+(lane&15))*80 + (uint32_t)((lane>>4)*8 + kc*16)*2);
        #pragma unroll
        for (int p=0;p<4;p++){
            uint32_t bf[4];
            ldsm4(bf, kb + (uint32_t)(p*16 + ((lane>>4)&1)*8 + (lane&7))*80
                        + (uint32_t)(kc*16 + ((lane>>3)&1)*8)*2);
            mma16816(s[2*p],  a, bf[0], bf[1]);
            mma16816(s[2*p+1],a, bf[2], bf[3]);
        }
    }

    const float scale=0.17677669529663687f;
    float mx1=-3.4e38f, mx2=-3.4e38f;
    #pragma unroll
    for (int nt=0;nt<8;nt++){
        mx1=fmaxf(mx1,fmaxf(s[nt][0],s[nt][1]));
        mx2=fmaxf(mx2,fmaxf(s[nt][2],s[nt][3]));
    }
    mx1=fmaxf(mx1,__shfl_xor_sync(~0u,mx1,1)); mx1=fmaxf(mx1,__shfl_xor_sync(~0u,mx1,2));
    mx2=fmaxf(mx2,__shfl_xor_sync(~0u,mx2,1)); mx2=fmaxf(mx2,__shfl_xor_sync(~0u,mx2,2));
    float sm1=0.f, sm2=0.f;
    #pragma unroll
    for (int nt=0;nt<8;nt++){
        s[nt][0]=__expf((s[nt][0]-mx1)*scale); s[nt][1]=__expf((s[nt][1]-mx1)*scale);
        s[nt][2]=__expf((s[nt][2]-mx2)*scale); s[nt][3]=__expf((s[nt][3]-mx2)*scale);
        sm1+=s[nt][0]+s[nt][1]; sm2+=s[nt][2]+s[nt][3];
    }
    sm1+=__shfl_xor_sync(~0u,sm1,1); sm1+=__shfl_xor_sync(~0u,sm1,2);
    sm2+=__shfl_xor_sync(~0u,sm2,1); sm2+=__shfl_xor_sync(~0u,sm2,2);
    float i1=1.f/sm1, i2=1.f/sm2;
    uint32_t ph1[8], ph2[8];
    #pragma unroll
    for (int nt=0;nt<8;nt++){
        __half2 t1=__floats2half2_rn(s[nt][0]*i1, s[nt][1]*i1);
        __half2 t2=__floats2half2_rn(s[nt][2]*i2, s[nt][3]*i2);
        ph1[nt]=*(uint32_t*)&t1; ph2[nt]=*(uint32_t*)&t2;
    }

    float o[4][4];
    #pragma unroll
    for (int nv=0;nv<4;nv++)
        #pragma unroll
        for (int q=0;q<4;q++) o[nv][q]=0.f;
    #pragma unroll
    for (int kc2=0;kc2<4;kc2++){
        uint32_t a[4]={ph1[2*kc2], ph2[2*kc2], ph1[2*kc2+1], ph2[2*kc2+1]};
        #pragma unroll
        for (int p=0;p<2;p++){
            uint32_t bf[4];
            ldsm4t(bf, vb + (uint32_t)(kc2*16 + ((lane>>3)&1)*8 + (lane&7))*80
                         + (uint32_t)((2*p + (lane>>4))*8)*2);
            mma16816(o[2*p],  a, bf[0], bf[1]);
            mma16816(o[2*p+1],a, bf[2], bf[3]);
        }
    }

    int lq=lane>>2, lrm=lane&3;
    int r1=b*64 + m0 + lq;
    #pragma unroll
    for (int nv=0;nv<4;nv++){
        int col=h*32 + nv*8 + lrm*2;
        __half2 t1=__floats2half2_rn(o[nv][0],o[nv][1]);
        __half2 t2=__floats2half2_rn(o[nv][2],o[nv][3]);
        *(uint32_t*)(g_aoh + (size_t)r1*256 + col)     = *(uint32_t*)&t1;
        *(uint32_t*)(g_aoh + (size_t)(r1+8)*256 + col) = *(uint32_t*)&t2;
    }
}

// ---------- prep (4-way ILP) ----------
__global__ void k_prep_pre(const float* __restrict__ pre_w, const float* __restrict__ pre_b,
                           const float* __restrict__ enc_w, const float* __restrict__ enc_b){
    int i=blockIdx.x, k=threadIdx.x;
    float v;
    if (k<256) v=pre_w[i*384+k];
    else {
        int kk=k-256;
        float v0=0.f,v1=0.f,v2=0.f,v3=0.f;
        const float* pw=pre_w+i*384+256;
        #pragma unroll 8
        for (int j=0;j<128;j+=4){
            v0+=pw[j]  *enc_w[(j)*128+kk];
            v1+=pw[j+1]*enc_w[(j+1)*128+kk];
            v2+=pw[j+2]*enc_w[(j+2)*128+kk];
            v3+=pw[j+3]*enc_w[(j+3)*128+kk];
        }
        v=(v0+v1)+(v2+v3);
    }
    h16 hv=__float2half(v);
    if (k<128)       g_wnode[i*128+k]=hv;
    else if (k<256)  g_wnode[(128+i)*128+(k-128)]=hv;
    else             g_wedge[i*128+(k-256)]=hv;
    if (k==0){
        const float* pw=pre_w+i*384+256;
        float t0=0.f,t1=0.f,t2=0.f,t3=0.f;
        #pragma unroll 8
        for (int j=0;j<128;j+=4){
            t0+=pw[j]*enc_b[j]; t1+=pw[j+1]*enc_b[j+1];
            t2+=pw[j+2]*enc_b[j+2]; t3+=pw[j+3]*enc_b[j+3];
        }
        g_bpre[i]=pre_b[i]+(t0+t1)+(t2+t3);
    }
}
// grid 385: blocks 0..383 build wstk; block 384 builds bias2
__global__ void k_prep_post(const float* __restrict__ linp_w, const float* __restrict__ post_w,
                            const float* __restrict__ post_b, const float* __restrict__ linp_b){
    int n=blockIdx.x, k=threadIdx.x;
    if (n==384){
        if (k<128){
            const float* lw=linp_w+k*128;
            float t0=0.f,t1=0.f,t2=0.f,t3=0.f;
            #pragma unroll 8
            for (int j=0;j<128;j+=4){
                t0+=lw[j]*post_b[j]; t1+=lw[j+1]*post_b[j+1];
                t2+=lw[j+2]*post_b[j+2]; t3+=lw[j+3]*post_b[j+3];
            }
            g_bias2[k]=linp_b[k]+(t0+t1)+(t2+t3);
        }
        return;
    }
    int s=n>>7, m=n&127;
    float v=0.f;
    int col=-1;
    if (k<128){ if (s==0) col=k; }
    else col=128+s*512+(k-128);
    if (col>=0){
        const float* lw=linp_w+m*128;
        float v0=0.f,v1=0.f,v2=0.f,v3=0.f;
        #pragma unroll 8
        for (int j=0;j<128;j+=4){
            v0+=lw[j]  *post_w[(size_t)(j)*1664+col];
            v1+=lw[j+1]*post_w[(size_t)(j+1)*1664+col];
            v2+=lw[j+2]*post_w[(size_t)(j+2)*1664+col];
            v3+=lw[j+3]*post_w[(size_t)(j+3)*1664+col];
        }
        v=(v0+v1)+(v2+v3);
    }
    g_wstk_h[n*640+k]=__float2half(v);
}

// ---------- CSR ----------
__global__ void k_deg(const int* __restrict__ ei){
    int e=blockIdx.x*blockDim.x+threadIdx.x;
    if (e<Ee) atomicAdd(&g_deg[ei[Ee+e]],1);
}
__global__ void __launch_bounds__(1024) k_scan(){
    __shared__ int part[1024];
    int tid=threadIdx.x; const int chunk=(Nn+1023)/1024;
    int beg=tid*chunk, end=min(beg+chunk,Nn);
    int s=0; for (int i=beg;i<end;i++) s+=g_deg[i];
    part[tid]=s; __syncthreads();
    for (int d=1;d<1024;d<<=1){ int v=part[tid]; if (tid>=d) v+=part[tid-d]; __syncthreads(); part[tid]=v; __syncthreads(); }
    int off=(tid==0)?0:part[tid-1];
    for (int i=beg;i<end;i++){ g_rowstart[i]=off; off+=g_deg[i]; }
    if (end==Nn) g_rowstart[Nn]=off;
}
__global__ void k_scatter(const int* __restrict__ ei){
    int e=blockIdx.x*blockDim.x+threadIdx.x;
    if (e<Ee){ int d=ei[Ee+e]; int p=atomicAdd(&g_cursor[d],1); g_eid[g_rowstart[d]+p]=e; }
}

// ---------- aggregation: warp-per-node, contiguous rows, P1-shift applied ----------
__global__ void __launch_bounds__(128) k_agg(float delta){
    int w=threadIdx.x>>5, lane=threadIdx.x&31;
    int n=blockIdx.x*4+w;
    if (n>=Nn) return;
    int s=g_rowstart[n], e=g_rowstart[n+1];
    int c4=lane*4;
    float su[4]={0,0,0,0}, sq[4]={0,0,0,0};
    float mx[4], mn[4];
    #pragma unroll
    for (int i=0;i<4;i++){ mx[i]=-3.402823466e38f; mn[i]=3.402823466e38f; }
    for (int j=s;j<e;j++){
        uint2 v=*(const uint2*)(g_Hh+(size_t)j*128+c4);
        __half2 h0=*(__half2*)&v.x, h1=*(__half2*)&v.y;
        float f[4]={__low2float(h0),__high2float(h0),__low2float(h1),__high2float(h1)};
        #pragma unroll
        for (int i=0;i<4;i++){ su[i]+=f[i]; sq[i]+=f[i]*f[i]; mx[i]=fmaxf(mx[i],f[i]); mn[i]=fminf(mn[i],f[i]); }
    }
    float cnt=(float)(e-s), den=fmaxf(cnt,1.f);
    uint2 up=*(const uint2*)(g_p12+(size_t)n*256+c4);
    __half2 q0=*(__half2*)&up.x, q1=*(__half2*)&up.y;
    float pf[4]={__low2float(q0),__high2float(q0),__low2float(q1),__high2float(q1)};
    float mean[4], sd[4];
    #pragma unroll
    for (int i=0;i<4;i++){
        mean[i]=su[i]/den;
        sd[i]=sqrtf(fmaxf(sq[i]/den-mean[i]*mean[i],0.f)+EPSf);
        if (cnt<=0.f){ mx[i]=0.f; mn[i]=0.f; }
        else { mean[i]+=pf[i]; mx[i]+=pf[i]; mn[i]+=pf[i]; }
    }
    size_t b6=(size_t)n*640;
    *(uint2*)(g_aggh+b6+c4)=*(const uint2*)(g_xgh+(size_t)n*128+c4);
    __half2 a0,a1;
    a0=__floats2half2_rn(mean[0],mean[1]); a1=__floats2half2_rn(mean[2],mean[3]);
    { uint2 u; u.x=*(uint32_t*)&a0; u.y=*(uint32_t*)&a1; *(uint2*)(g_aggh+b6+128+c4)=u; }
    a0=__floats2half2_rn(mx[0],mx[1]); a1=__floats2half2_rn(mx[2],mx[3]);
    { uint2 u; u.x=*(uint32_t*)&a0; u.y=*(uint32_t*)&a1; *(uint2*)(g_aggh+b6+256+c4)=u; }
    a0=__floats2half2_rn(mn[0],mn[1]); a1=__floats2half2_rn(mn[2],mn[3]);
    { uint2 u; u.x=*(uint32_t*)&a0; u.y=*(uint32_t*)&a1; *(uint2*)(g_aggh+b6+384+c4)=u; }
    a0=__floats2half2_rn(sd[0],sd[1]); a1=__floats2half2_rn(sd[2],sd[3]);
    { uint2 u; u.x=*(uint32_t*)&a0; u.y=*(uint32_t*)&a1; *(uint2*)(g_aggh+b6+512+c4)=u; }
    if (lane==0){ float dc=fmaxf(cnt,1.f), lg=logf(dc+1.f); g_amp[n]=lg/delta; g_att[n]=delta/lg; }
}

// ---------- final (fp16 Y, fp16 x) ----------
__global__ void k_final(const float* __restrict__ bg, const float* __restrict__ bb,
                        float* __restrict__ out){
    int i=blockIdx.x*blockDim.x+threadIdx.x;
    if (i<Nn*128){
        int c=i&127;
        float mu=g_bnsum[c]*(1.f/Nn);
        float var=g_bnsq[c]*(1.f/Nn)-mu*mu;
        float y=bg[c]*(__half2float(g_Yh[i])-mu)*rsqrtf(var+EPSf)+bb[c];
        out[i]=(__half2float(g_xgh[i])+fmaxf(y,0.f))*0.5f;
    }
}

// ---------- launch ----------
extern "C" void kernel_launch(void* const* d_in, const int* in_sizes, int n_in,
                              void* d_out, int out_size)
{
    const float* x_tab=(const float*)d_in[0];
    const float* x_gnn=(const float*)d_in[1];
    const int*   ei   =(const int*)  d_in[2];
    const float* ea   =(const float*)d_in[3];
    const float* ipw=(const float*)d_in[4];  const float* ipb=(const float*)d_in[5];
    const float* opw=(const float*)d_in[6];  const float* opb=(const float*)d_in[7];
    const float* l1w=(const float*)d_in[8];  const float* l1b=(const float*)d_in[9];
    const float* l2w=(const float*)d_in[10]; const float* l2b=(const float*)d_in[11];
    const float* n1g=(const float*)d_in[12]; const float* n1b=(const float*)d_in[13];
    const float* n2g=(const float*)d_in[14]; const float* n2b=(const float*)d_in[15];
    const float* tng=(const float*)d_in[16]; const float* tnb=(const float*)d_in[17];
    const float* encw=(const float*)d_in[18];const float* encb=(const float*)d_in[19];
    const float* prew=(const float*)d_in[20];const float* preb=(const float*)d_in[21];
    const float* postw=(const float*)d_in[22];const float* postb=(const float*)d_in[23];
    const float* lpw=(const float*)d_in[24]; const float* lpb=(const float*)d_in[25];
    const float* bng=(const float*)d_in[26]; const float* bnb=(const float*)d_in[27];

    float* out_tab=(float*)d_out;
    float* out_gnn=(float*)d_out+TAB_OUT;
    float* out_ea =(float*)d_out+TAB_OUT+GNN_OUT;

    cudaFuncSetAttribute(k_mm<1>,  cudaFuncAttributeMaxDynamicSharedMemorySize, GEMM_SMEM);
    cudaFuncSetAttribute(k_mm<2>,  cudaFuncAttributeMaxDynamicSharedMemorySize, GEMM_SMEM);
    cudaFuncSetAttribute(k_mmln<1>, cudaFuncAttributeMaxDynamicSharedMemorySize, FSM);
    cudaFuncSetAttribute(k_mmln<2>, cudaFuncAttributeMaxDynamicSharedMemorySize, FSM);
    cudaFuncSetAttribute(k_mm_pre2, cudaFuncAttributeMaxDynamicSharedMemorySize, PRE_SMEM);
    cudaFuncSetAttribute(k_post3,  cudaFuncAttributeMaxDynamicSharedMemorySize, POST_SMEM);

    #define SYM(p,s) void* p; cudaGetSymbolAddress(&p, s)
    SYM(qkvh,g_qkvh); SYM(xth,g_xth); SYM(aoh,g_aoh);
    SYM(h1h,g_h1h); SYM(f1h,g_f1h);
    SYM(wqh,g_wq_h); SYM(woh,g_wo_h); SYM(w1h,g_w1_h); SYM(w2h,g_w2_h);
    SYM(xgh,g_xgh); SYM(eah,g_eah); SYM(p12,g_p12);
    SYM(wnode,g_wnode); SYM(bz,g_bz);

    const double dhh[5]={0.0,20000.0,30000.0,30000.0,20000.0};
    double sa=0.0,ta=0.0;
    for (int i=0;i<5;i++){ sa+=log((double)i+1.0)*dhh[i]; ta+=dhh[i]; }
    float delta=(float)(sa/ta);

    // one extra stream + two events (proven leak-free structure)
    cudaStream_t s1;
    cudaStreamCreateWithFlags(&s1, cudaStreamNonBlocking);
    cudaEvent_t ev0, ev1;
    cudaEventCreateWithFlags(&ev0, cudaEventDisableTiming);
    cudaEventCreateWithFlags(&ev1, cudaEventDisableTiming);
    cudaEventRecord(ev0, 0);
    cudaStreamWaitEvent(s1, ev0, 0);

    // ======== GNN branch on s1 ========
    k_init_gnn<<<2048,256,0,s1>>>(x_gnn);
    k_ea16<<<4096,256,0,s1>>>((const float4*)ea,(float4*)out_ea,(uint2*)eah,(Ee*128)/4);
    k_prep_pre<<<128,384,0,s1>>>(prew,preb,encw,encb);
    k_prep_post<<<385,640,0,s1>>>(lpw,postw,postb,lpb);
    k_deg<<<CDIV(Ee,256),256,0,s1>>>(ei);
    k_scan<<<1,1024,0,s1>>>();
    k_scatter<<<CDIV(Ee,256),256,0,s1>>>(ei);
    k_mm<2><<<dim3(2,CDIV(Nn,128)),256,GEMM_SMEM,s1>>>((h16*)xgh,(h16*)wnode,(float*)bz,(h16*)p12,Nn,256,128);
    k_mm_pre2<<<CDIV(NTILES_TOT,PTILES),256,PRE_SMEM,s1>>>(ei);
    k_agg<<<CDIV(Nn,4),128,0,s1>>>(delta);
    k_post3<<<CDIV(Nn,128),256,POST_SMEM,s1>>>();
    k_final<<<CDIV(Nn*128,256),256,0,s1>>>(bng,bnb,out_gnn);
    cudaEventRecord(ev1, s1);

    // ======== tab branch on default stream ========
    k_r16<<<2048,256>>>(x_tab,(h16*)xth,(size_t)RT*256);
    k_r16<<<512,256>>>(ipw,(h16*)wqh,768*256);
    k_r16<<<256,256>>>(opw,(h16*)woh,256*256);
    k_r16<<<512,256>>>(l1w,(h16*)w1h,1024*256);
    k_r16<<<512,256>>>(l2w,(h16*)w2h,256*1024);
    k_mm<2><<<dim3(6,512),256,GEMM_SMEM>>>((h16*)xth,(h16*)wqh,ipb,(h16*)qkvh,RT,768,256);
    k_attn<<<8192,128>>>((h16*)qkvh);
    k_mmln<1><<<512,512,FSM>>>((h16*)aoh,(h16*)woh,opb,(h16*)xth,n1g,n1b,0,0,0,256);
    k_mm<1><<<dim3(8,512),256,GEMM_SMEM>>>((h16*)h1h,(h16*)w1h,l1b,(h16*)f1h,RT,1024,256);
    k_mmln<2><<<512,512,FSM>>>((h16*)f1h,(h16*)w2h,l2b,(h16*)h1h,n2g,n2b,tng,tnb,out_tab,1024);

    cudaStreamWaitEvent((cudaStream_t)0, ev1, 0);
}

// round 17
// speedup vs baseline: 1.0223x; 1.0223x over previous
#include <cuda_runtime.h>
#include <cuda_fp16.h>
#include <math.h>
#include <stdint.h>

#define Nn 100000
#define Ee 400000
#define RT 65536
#define EPSf 1e-5f
#define TAB_OUT ((size_t)RT*256)
#define GNN_OUT ((size_t)Nn*128)
#define CDIV(a,b) (((a)+(b)-1)/(b))
typedef __half h16;

// ---------- PTX helpers ----------
__device__ __forceinline__ uint32_t smem_u32(const void* p){
    uint32_t a; asm("{ .reg .u64 t; cvta.to.shared.u64 t, %1; cvt.u32.u64 %0, t; }":"=r"(a):"l"(p)); return a;
}
#define CP16(d,s)   asm volatile("cp.async.cg.shared.global [%0], [%1], 16;"::"r"((uint32_t)(d)),"l"(s))
#define CPC()       asm volatile("cp.async.commit_group;":::"memory")
#define CPW(n)      asm volatile("cp.async.wait_group %0;"::"n"(n):"memory")

__device__ __forceinline__ void ldsm4(uint32_t* r, uint32_t addr){
    asm volatile("ldmatrix.sync.aligned.m8n8.x4.shared.b16 {%0,%1,%2,%3}, [%4];"
        : "=r"(r[0]),"=r"(r[1]),"=r"(r[2]),"=r"(r[3]) : "r"(addr));
}
__device__ __forceinline__ void ldsm4t(uint32_t* r, uint32_t addr){
    asm volatile("ldmatrix.sync.aligned.m8n8.x4.trans.shared.b16 {%0,%1,%2,%3}, [%4];"
        : "=r"(r[0]),"=r"(r[1]),"=r"(r[2]),"=r"(r[3]) : "r"(addr));
}
__device__ __forceinline__ void mma16816(float* d, const uint32_t* a, uint32_t b0, uint32_t b1){
    asm volatile("mma.sync.aligned.m16n8k16.row.col.f32.f16.f16.f32 "
        "{%0,%1,%2,%3},{%4,%5,%6,%7},{%8,%9},{%0,%1,%2,%3};"
        : "+f"(d[0]),"+f"(d[1]),"+f"(d[2]),"+f"(d[3])
        : "r"(a[0]),"r"(a[1]),"r"(a[2]),"r"(a[3]),"r"(b0),"r"(b1));
}

// ---------- scratch ----------
__device__ __align__(256) h16  g_qkvh[(size_t)RT*768];
__device__ __align__(256) h16  g_xth[(size_t)RT*256];
__device__ __align__(256) h16  g_aoh[(size_t)RT*256];
__device__ __align__(256) h16  g_h1h[(size_t)RT*256];
__device__ __align__(256) h16  g_f1h[(size_t)RT*1024];
__device__ __align__(256) h16 g_wq_h[768*256];
__device__ __align__(256) h16 g_wo_h[256*256];
__device__ __align__(256) h16 g_w1_h[1024*256];
__device__ __align__(256) h16 g_w2_h[256*1024];
__device__ __align__(256) h16 g_wnode[256*128];
__device__ __align__(256) h16 g_wedge[128*128];
__device__ __align__(256) h16 g_wstk_h[384*640];
__device__ float g_bpre[128], g_bias2[128];
__device__ float g_bz[256];     // stays zero
__device__ __align__(256) h16 g_xgh[(size_t)Nn*128];
__device__ __align__(256) h16 g_p12[(size_t)Nn*256];
__device__ __align__(256) h16 g_eah[(size_t)Ee*128];
__device__ __align__(256) h16 g_Hh[(size_t)Ee*128];
__device__ __align__(256) h16 g_aggh[(size_t)Nn*640];
__device__ __align__(256) h16 g_Yh[(size_t)Nn*128];
__device__ float g_amp[Nn], g_att[Nn];
__device__ int g_deg[Nn], g_rowstart[Nn+1], g_cursor[Nn], g_eid[Ee];
__device__ float g_bnsum[128], g_bnsq[128];

// ---------- converters ----------
__global__ void k_r16(const float* __restrict__ s, h16* __restrict__ d, size_t n){
    for (size_t i=blockIdx.x*(size_t)blockDim.x+threadIdx.x; i<n; i+=(size_t)gridDim.x*blockDim.x)
        d[i]=__float2half(s[i]);
}
// single kernel converting all four tab weight matrices
#define WQ_N (768*256)
#define WO_N (256*256)
#define W1_N (1024*256)
#define W2_N (256*1024)
__global__ void k_wconv(const float* __restrict__ ipw, const float* __restrict__ opw,
                        const float* __restrict__ l1w, const float* __restrict__ l2w){
    const int total = WQ_N + WO_N + W1_N + W2_N;
    for (int i=blockIdx.x*blockDim.x+threadIdx.x; i<total; i+=gridDim.x*blockDim.x){
        if (i < WQ_N) g_wq_h[i]=__float2half(ipw[i]);
        else if (i < WQ_N+WO_N) g_wo_h[i-WQ_N]=__float2half(opw[i-WQ_N]);
        else if (i < WQ_N+WO_N+W1_N) g_w1_h[i-WQ_N-WO_N]=__float2half(l1w[i-WQ_N-WO_N]);
        else g_w2_h[i-WQ_N-WO_N-W1_N]=__float2half(l2w[i-WQ_N-WO_N-W1_N]);
    }
}
__global__ void k_ea16(const float4* __restrict__ s, float4* __restrict__ out, uint2* __restrict__ d, int n4){
    for (int i=blockIdx.x*blockDim.x+threadIdx.x; i<n4; i+=gridDim.x*blockDim.x){
        float4 v=s[i]; out[i]=v;
        __half2 p0=__floats2half2_rn(v.x,v.y), p1=__floats2half2_rn(v.z,v.w);
        uint2 u; u.x=*(uint32_t*)&p0; u.y=*(uint32_t*)&p1;
        d[i]=u;
    }
}
__global__ void k_zero(){
    int i=blockIdx.x*blockDim.x+threadIdx.x;
    if (i<Nn){ g_deg[i]=0; g_cursor[i]=0; }
    if (i<128){ g_bnsum[i]=0.f; g_bnsq[i]=0.f; }
}

// ===================================================================
// fp16 single-term GEMM (N-tiled): C = A16 @ W16^T + bias
// EPI 1: relu+fp16; 2: fp16+bias
// ===================================================================
#define STGS 4
#define STAGE_BYTES 16384
#define GEMM_SMEM (STGS*STAGE_BYTES)

template<int EPI>
__global__ void __launch_bounds__(256) k_mm(
    const h16* __restrict__ A, const h16* __restrict__ Wh,
    const float* __restrict__ bias, h16* __restrict__ Ch,
    int M, int Ntot, int K)
{
    extern __shared__ __align__(128) char smem[];
    uint32_t sb = smem_u32(smem);
    int tid=threadIdx.x, lane=tid&31, wid=tid>>5;
    int m0=blockIdx.y*128, n0=blockIdx.x*128;
    int wm=(wid&1)*64, wn=(wid>>1)*32;

    int lr=tid>>1, lc=tid&1;
    uint32_t wb = ((uint32_t)(lr>>3)<<9) + ((uint32_t)(lr&7)<<4);
    uint32_t wd0 = wb + ((uint32_t)(2*lc)<<7);
    uint32_t wd1 = wb + ((uint32_t)(2*lc+1)<<7);
    int ar=min(m0+lr, M-1);
    const h16 *pA = A + (size_t)ar*K + lc*16;
    const h16 *pWh= Wh+ (size_t)(n0+lr)*K + lc*16;
    int nst=K>>5;

#define LDST(st,k0) do{ uint32_t _o=sb+(uint32_t)(st)*STAGE_BYTES; int _k=(k0); \
    CP16(_o+wd0, pA+_k);        CP16(_o+wd1, pA+_k+8); \
    CP16(_o+8192+wd0, pWh+_k);  CP16(_o+8192+wd1, pWh+_k+8); \
    CPC(); }while(0)

    int l7=lane&7, t8=(lane>>3)&1, t16=lane>>4;
    uint32_t fb = ((uint32_t)l7<<4) + ((uint32_t)t16<<7);
    uint32_t bA[4], bB[2];
    #pragma unroll
    for (int m=0;m<4;m++) bA[m] = ((uint32_t)((wm>>3)+2*m+t8)<<9) + fb;
    #pragma unroll
    for (int g=0;g<2;g++) bB[g] = 8192u + ((uint32_t)((wn>>3)+2*g+t8)<<9) + fb;

    float acc[4][4][4];
    #pragma unroll
    for (int m=0;m<4;m++)
        #pragma unroll
        for (int nf=0;nf<4;nf++)
            #pragma unroll
            for (int q=0;q<4;q++) acc[m][nf][q]=0.f;

    LDST(0,0);
    if (nst>1) LDST(1,32);
    if (nst>2) LDST(2,64);

    for (int s=0;s<nst;s++){
        if (s < nst-2) CPW(2); else if (s==nst-2) CPW(1); else CPW(0);
        __syncthreads();
        if (s+3<nst) LDST((s+3)&3, (s+3)*32);
        uint32_t st = sb + (uint32_t)(s&3)*STAGE_BYTES;
        #pragma unroll
        for (int ks=0;ks<2;ks++){
            uint32_t ko = (uint32_t)ks<<8;
            uint32_t Af[4][4], Bh[2][4];
            #pragma unroll
            for (int m=0;m<4;m++) ldsm4(Af[m], st + bA[m] + ko);
            #pragma unroll
            for (int g=0;g<2;g++) ldsm4(Bh[g], st + bB[g] + ko);
            #pragma unroll
            for (int m=0;m<4;m++)
                #pragma unroll
                for (int nf=0;nf<4;nf++){
                    int g=nf>>1,o=nf&1;
                    mma16816(acc[m][nf],Af[m],Bh[g][o],Bh[g][2+o]);
                }
        }
    }
#undef LDST

    int lq=lane>>2, lrm=lane&3;
    #pragma unroll
    for (int m=0;m<4;m++)
        #pragma unroll
        for (int nf=0;nf<4;nf++){
            int gm=m0+wm+m*16+lq;
            int gn=n0+wn+nf*8+lrm*2;
            float b0=bias[gn], b1=bias[gn+1];
            float* a4=acc[m][nf];
            #pragma unroll
            for (int hr=0;hr<2;hr++){
                int r=gm+hr*8;
                if (r<M){
                    float v0=a4[hr*2+0]+b0, v1=a4[hr*2+1]+b1;
                    if (EPI==1){ v0=fmaxf(v0,0.f); v1=fmaxf(v1,0.f); }
                    __half2 p=__floats2half2_rn(v0,v1);
                    *(uint32_t*)(Ch+(size_t)r*Ntot+gn)=*(uint32_t*)&p;
                }
            }
        }
}

// ===================================================================
// fused full-row GEMM + LayerNorm, single-term W, fp16 residual.
// FLN 1: h1 = LN1(res16 + A@W + b) -> g_h1h;  FLN 2: LNt(LN2(...)) -> fp32
// ===================================================================
#define FST 24576
#define FSM (4*FST)

template<int FLN>
__global__ void __launch_bounds__(512) k_mmln(
    const h16* __restrict__ A, const h16* __restrict__ Wh,
    const float* __restrict__ bias, const h16* __restrict__ res,
    const float* __restrict__ g1, const float* __restrict__ b1,
    const float* __restrict__ g2, const float* __restrict__ b2,
    float* __restrict__ outf, int K)
{
    extern __shared__ __align__(128) char smem[];
    uint32_t sb = smem_u32(smem);
    int tid=threadIdx.x, lane=tid&31, wid=tid>>5;
    int m0=blockIdx.x*128;
    int wm=(wid&1)*64, wn=(wid>>1)*32;

    int rowA=tid>>2, cA=tid&3;
    const h16 *pA  = A  + (size_t)(m0+rowA)*K + cA*8;
    const h16 *pW0h= Wh + (size_t)rowA*K + cA*8;
    const h16 *pW1h= Wh + (size_t)(rowA+128)*K + cA*8;
    uint32_t dA  = ((uint32_t)(rowA>>3)<<9)+((uint32_t)(rowA&7)<<4)+((uint32_t)cA<<7);
    uint32_t dW0 = 8192u + dA;
    int nst=K>>5;

#define LDF(st,k0) do{ uint32_t _o=sb+(uint32_t)(st)*FST; int _k=(k0); \
    CP16(_o+dA, pA+_k); \
    CP16(_o+dW0, pW0h+_k); CP16(_o+dW0+8192, pW1h+_k); \
    CPC(); }while(0)

    int l7=lane&7, t8=(lane>>3)&1, t16=lane>>4;
    uint32_t fb = ((uint32_t)l7<<4) + ((uint32_t)t16<<7);
    uint32_t bA[4], bB[2];
    #pragma unroll
    for (int m=0;m<4;m++) bA[m] = ((uint32_t)((wm>>3)+2*m+t8)<<9) + fb;
    #pragma unroll
    for (int g=0;g<2;g++) bB[g] = 8192u + ((uint32_t)((wn>>3)+2*g+t8)<<9) + fb;

    float acc[4][4][4];
    #pragma unroll
    for (int m=0;m<4;m++)
        #pragma unroll
        for (int nf=0;nf<4;nf++)
            #pragma unroll
            for (int q=0;q<4;q++) acc[m][nf][q]=0.f;

    LDF(0,0); LDF(1,32); LDF(2,64);

    for (int s=0;s<nst;s++){
        if (s < nst-2) CPW(2); else if (s==nst-2) CPW(1); else CPW(0);
        __syncthreads();
        if (s+3<nst) LDF((s+3)&3, (s+3)*32);
        uint32_t st = sb + (uint32_t)(s&3)*FST;
        #pragma unroll
        for (int ks=0;ks<2;ks++){
            uint32_t ko = (uint32_t)ks<<8;
            uint32_t Af[4][4], Bh[2][4];
            #pragma unroll
            for (int m=0;m<4;m++) ldsm4(Af[m], st + bA[m] + ko);
            #pragma unroll
            for (int g=0;g<2;g++) ldsm4(Bh[g], st + bB[g] + ko);
            #pragma unroll
            for (int m=0;m<4;m++)
                #pragma unroll
                for (int nf=0;nf<4;nf++){
                    int g=nf>>1,o=nf&1;
                    mma16816(acc[m][nf],Af[m],Bh[g][o],Bh[g][2+o]);
                }
        }
    }
#undef LDF

    __syncthreads();
    float* red = (float*)smem;
    int lq=lane>>2, lrm=lane&3, nw=wid>>1;

    #pragma unroll
    for (int m=0;m<4;m++)
        #pragma unroll
        for (int nf=0;nf<4;nf++){
            int gn=wn+nf*8+lrm*2;
            float b0=bias[gn], b1v=bias[gn+1];
            #pragma unroll
            for (int hr=0;hr<2;hr++){
                int r=m0+wm+m*16+lq+hr*8;
                uint32_t xr=*(const uint32_t*)(res+(size_t)r*256+gn);
                __half2 hx=*(__half2*)&xr;
                acc[m][nf][2*hr]  += b0 + __low2float(hx);
                acc[m][nf][2*hr+1]+= b1v+ __high2float(hx);
            }
        }
    #pragma unroll
    for (int m=0;m<4;m++)
        #pragma unroll
        for (int hr=0;hr<2;hr++){
            float ps=0.f, pq=0.f;
            #pragma unroll
            for (int nf=0;nf<4;nf++){
                float a0=acc[m][nf][2*hr], a1=acc[m][nf][2*hr+1];
                ps+=a0+a1; pq+=a0*a0+a1*a1;
            }
            ps+=__shfl_xor_sync(~0u,ps,1); ps+=__shfl_xor_sync(~0u,ps,2);
            pq+=__shfl_xor_sync(~0u,pq,1); pq+=__shfl_xor_sync(~0u,pq,2);
            if (lrm==0){ int rl=wm+m*16+lq+hr*8; red[rl*8+nw]=ps; red[1024+rl*8+nw]=pq; }
        }
    __syncthreads();
    float mu[4][2], inv[4][2];
    #pragma unroll
    for (int m=0;m<4;m++)
        #pragma unroll
        for (int hr=0;hr<2;hr++){
            int rl=wm+m*16+lq+hr*8;
            float s=0.f,q=0.f;
            #pragma unroll
            for (int k=0;k<8;k++){ s+=red[rl*8+k]; q+=red[1024+rl*8+k]; }
            float m1=s*(1.f/256.f);
            mu[m][hr]=m1; inv[m][hr]=rsqrtf(q*(1.f/256.f)-m1*m1+EPSf);
        }
    #pragma unroll
    for (int m=0;m<4;m++)
        #pragma unroll
        for (int nf=0;nf<4;nf++){
            int gn=wn+nf*8+lrm*2;
            float gg0=g1[gn], gg1=g1[gn+1], bb0=b1[gn], bb1=b1[gn+1];
            #pragma unroll
            for (int hr=0;hr<2;hr++){
                acc[m][nf][2*hr]  = gg0*(acc[m][nf][2*hr]  -mu[m][hr])*inv[m][hr]+bb0;
                acc[m][nf][2*hr+1]= gg1*(acc[m][nf][2*hr+1]-mu[m][hr])*inv[m][hr]+bb1;
            }
        }
    if (FLN==1){
        #pragma unroll
        for (int m=0;m<4;m++)
            #pragma unroll
            for (int nf=0;nf<4;nf++){
                int gn=wn+nf*8+lrm*2;
                #pragma unroll
                for (int hr=0;hr<2;hr++){
                    int r=m0+wm+m*16+lq+hr*8;
                    __half2 p=__floats2half2_rn(acc[m][nf][2*hr],acc[m][nf][2*hr+1]);
                    *(uint32_t*)(g_h1h+(size_t)r*256+gn)=*(uint32_t*)&p;
                }
            }
    } else {
        __syncthreads();
        #pragma unroll
        for (int m=0;m<4;m++)
            #pragma unroll
            for (int hr=0;hr<2;hr++){
                float ps=0.f,pq=0.f;
                #pragma unroll
                for (int nf=0;nf<4;nf++){
                    float a0=acc[m][nf][2*hr], a1=acc[m][nf][2*hr+1];
                    ps+=a0+a1; pq+=a0*a0+a1*a1;
                }
                ps+=__shfl_xor_sync(~0u,ps,1); ps+=__shfl_xor_sync(~0u,ps,2);
                pq+=__shfl_xor_sync(~0u,pq,1); pq+=__shfl_xor_sync(~0u,pq,2);
                if (lrm==0){ int rl=wm+m*16+lq+hr*8; red[rl*8+nw]=ps; red[1024+rl*8+nw]=pq; }
            }
        __syncthreads();
        #pragma unroll
        for (int m=0;m<4;m++)
            #pragma unroll
            for (int hr=0;hr<2;hr++){
                int rl=wm+m*16+lq+hr*8;
                float s=0.f,q=0.f;
                #pragma unroll
                for (int k=0;k<8;k++){ s+=red[rl*8+k]; q+=red[1024+rl*8+k]; }
                float m1=s*(1.f/256.f);
                mu[m][hr]=m1; inv[m][hr]=rsqrtf(q*(1.f/256.f)-m1*m1+EPSf);
            }
        #pragma unroll
        for (int m=0;m<4;m++)
            #pragma unroll
            for (int nf=0;nf<4;nf++){
                int gn=wn+nf*8+lrm*2;
                float gg0=g2[gn], gg1=g2[gn+1], bb0=b2[gn], bb1=b2[gn+1];
                #pragma unroll
                for (int hr=0;hr<2;hr++){
                    int r=m0+wm+m*16+lq+hr*8;
                    float v0=gg0*(acc[m][nf][2*hr]  -mu[m][hr])*inv[m][hr]+bb0;
                    float v1=gg1*(acc[m][nf][2*hr+1]-mu[m][hr])*inv[m][hr]+bb1;
                    *(float2*)(outf+(size_t)r*256+gn)=make_float2(v0,v1);
                }
            }
    }
}

// ===================================================================
// edge GEMM (factored, P1-shifted): H[r] = ea[eid[r]]@Wedge^T + bpre + P2[src]
// (round-15 per-tile version)
// ===================================================================
#define PSTG 16384
#define PRE_SMEM (4*PSTG)

__global__ void __launch_bounds__(256) k_mm_pre2(const int* __restrict__ ei)
{
    extern __shared__ __align__(128) char smem[];
    uint32_t sb = smem_u32(smem);
    int tid=threadIdx.x, lane=tid&31, wid=tid>>5;
    int m0=blockIdx.x*128;
    int wm=(wid&1)*64, wn=(wid>>1)*32;

    int lr=tid>>1, lc=tid&1;
    uint32_t wb = ((uint32_t)(lr>>3)<<9) + ((uint32_t)(lr&7)<<4);
    uint32_t wd0 = wb + ((uint32_t)(2*lc)<<7);
    uint32_t wd1 = wb + ((uint32_t)(2*lc+1)<<7);
    int e=g_eid[m0+lr];
    const h16 *pA = g_eah + (size_t)e*128 + lc*16;
    const h16 *pW = g_wedge + (size_t)lr*128 + lc*16;
    const int nst=4;

#define LDSTP(st,k0) do{ uint32_t _o=sb+(uint32_t)(st)*PSTG; int _k=(k0); \
    CP16(_o+wd0, pA+_k);        CP16(_o+wd1, pA+_k+8); \
    CP16(_o+8192+wd0, pW+_k);   CP16(_o+8192+wd1, pW+_k+8); \
    CPC(); }while(0)

    int l7=lane&7, t8=(lane>>3)&1, t16=lane>>4;
    uint32_t fb = ((uint32_t)l7<<4) + ((uint32_t)t16<<7);
    uint32_t bA[4], bB[2];
    #pragma unroll
    for (int m=0;m<4;m++) bA[m] = ((uint32_t)((wm>>3)+2*m+t8)<<9) + fb;
    #pragma unroll
    for (int g=0;g<2;g++) bB[g] = 8192u + ((uint32_t)((wn>>3)+2*g+t8)<<9) + fb;

    float acc[4][4][4];
    #pragma unroll
    for (int m=0;m<4;m++)
        #pragma unroll
        for (int nf=0;nf<4;nf++)
            #pragma unroll
            for (int q=0;q<4;q++) acc[m][nf][q]=0.f;

    LDSTP(0,0); LDSTP(1,32); LDSTP(2,64);

    for (int s=0;s<nst;s++){
        if (s < nst-2) CPW(2); else if (s==nst-2) CPW(1); else CPW(0);
        __syncthreads();
        if (s+3<nst) LDSTP((s+3)&3, (s+3)*32);
        uint32_t st = sb + (uint32_t)(s&3)*PSTG;
        #pragma unroll
        for (int ks=0;ks<2;ks++){
            uint32_t ko = (uint32_t)ks<<8;
            uint32_t Af[4][4], Bh[2][4];
            #pragma unroll
            for (int m=0;m<4;m++) ldsm4(Af[m], st + bA[m] + ko);
            #pragma unroll
            for (int g=0;g<2;g++) ldsm4(Bh[g], st + bB[g] + ko);
            #pragma unroll
            for (int m=0;m<4;m++)
                #pragma unroll
                for (int nf=0;nf<4;nf++){
                    int g=nf>>1,o=nf&1;
                    mma16816(acc[m][nf],Af[m],Bh[g][o],Bh[g][2+o]);
                }
        }
    }
#undef LDSTP

    int lq=lane>>2, lrm=lane&3;
    #pragma unroll
    for (int m=0;m<4;m++)
        #pragma unroll
        for (int hr=0;hr<2;hr++){
            int r=m0+wm+m*16+lq+hr*8;
            int e2=g_eid[r];
            int vs=ei[e2];
            const h16* p2=g_p12+(size_t)vs*256+128;
            #pragma unroll
            for (int nf=0;nf<4;nf++){
                int gn=wn+nf*8+lrm*2;
                uint32_t u2=*(const uint32_t*)(p2+gn);
                __half2 h2v=*(__half2*)&u2;
                float v0=acc[m][nf][2*hr]  +g_bpre[gn]  +__low2float(h2v);
                float v1=acc[m][nf][2*hr+1]+g_bpre[gn+1]+__high2float(h2v);
                __half2 p=__floats2half2_rn(v0,v1);
                *(uint32_t*)(g_Hh+(size_t)r*128+gn)=*(uint32_t*)&p;
            }
        }
}

// ===================================================================
// post GEMM two-pass (A loaded once in pass B), fused BN stats, Y fp16
// ===================================================================
#define QSTG 24576
#define POST_SMEM (4*QSTG)

__global__ void __launch_bounds__(256) k_post3()
{
    extern __shared__ __align__(128) char smem[];
    uint32_t sb = smem_u32(smem);
    int tid=threadIdx.x, lane=tid&31, wid=tid>>5;
    int m0=blockIdx.x*128;
    int wm=(wid&1)*64, wn=(wid>>1)*32;

    int lr=tid>>1, lc=tid&1;
    uint32_t wb = ((uint32_t)(lr>>3)<<9) + ((uint32_t)(lr&7)<<4);
    uint32_t wd0 = wb + ((uint32_t)(2*lc)<<7);
    uint32_t wd1 = wb + ((uint32_t)(2*lc+1)<<7);
    int ar=min(m0+lr, Nn-1);
    const h16 *pA = g_aggh + (size_t)ar*640 + lc*16;
    const int nst=36;

#define LDQ(st,c) do{ uint32_t _o=sb+(uint32_t)(st)*QSTG; \
    int _k = ((c)<20)? (c)*32 : 128+((c)-20)*32; \
    CP16(_o+wd0, pA+_k); CP16(_o+wd1, pA+_k+8); \
    if ((c)<20){ \
        const h16* _w=g_wstk_h+(size_t)lr*640+_k+lc*16; \
        CP16(_o+8192+wd0,_w); CP16(_o+8192+wd1,_w+8); \
    } else { \
        const h16* _w1=g_wstk_h+(size_t)(128+lr)*640+_k+lc*16; \
        const h16* _w2=g_wstk_h+(size_t)(256+lr)*640+_k+lc*16; \
        CP16(_o+8192+wd0,_w1);  CP16(_o+8192+wd1,_w1+8); \
        CP16(_o+16384+wd0,_w2); CP16(_o+16384+wd1,_w2+8); \
    } \
    CPC(); }while(0)

    int l7=lane&7, t8=(lane>>3)&1, t16=lane>>4;
    uint32_t fb = ((uint32_t)l7<<4) + ((uint32_t)t16<<7);
    uint32_t bA[4], bB[2];
    #pragma unroll
    for (int m=0;m<4;m++) bA[m] = ((uint32_t)((wm>>3)+2*m+t8)<<9) + fb;
    #pragma unroll
    for (int g=0;g<2;g++) bB[g] = 8192u + ((uint32_t)((wn>>3)+2*g+t8)<<9) + fb;

    int lq=lane>>2, lrm=lane&3;
    float ampv[4][2], attv[4][2];
    #pragma unroll
    for (int m=0;m<4;m++)
        #pragma unroll
        for (int hr=0;hr<2;hr++){
            int r=min(m0+wm+m*16+lq+hr*8, Nn-1);
            ampv[m][hr]=g_amp[r]; attv[m][hr]=g_att[r];
        }

    float accM[4][4][4], accT1[4][4][4], accT2[4][4][4];
    #pragma unroll
    for (int m=0;m<4;m++)
        #pragma unroll
        for (int nf=0;nf<4;nf++)
            #pragma unroll
            for (int q=0;q<4;q++){ accM[m][nf][q]=0.f; accT1[m][nf][q]=0.f; accT2[m][nf][q]=0.f; }

    LDQ(0,0); LDQ(1,1); LDQ(2,2);

    for (int s=0;s<nst;s++){
        if (s < nst-2) CPW(2); else if (s==nst-2) CPW(1); else CPW(0);
        __syncthreads();
        if (s+3<nst) LDQ((s+3)&3, s+3);
        uint32_t st = sb + (uint32_t)(s&3)*QSTG;
        if (s<20){
            #pragma unroll
            for (int ks=0;ks<2;ks++){
                uint32_t ko = (uint32_t)ks<<8;
                uint32_t Af[4][4], B1[2][4];
                #pragma unroll
                for (int m=0;m<4;m++) ldsm4(Af[m], st + bA[m] + ko);
                #pragma unroll
                for (int g=0;g<2;g++) ldsm4(B1[g], st + bB[g] + ko);
                #pragma unroll
                for (int m=0;m<4;m++)
                    #pragma unroll
                    for (int nf=0;nf<4;nf++){
                        int g=nf>>1,o=nf&1;
                        mma16816(accM[m][nf],Af[m],B1[g][o],B1[g][2+o]);
                    }
            }
        } else {
            #pragma unroll
            for (int ks=0;ks<2;ks++){
                uint32_t ko = (uint32_t)ks<<8;
                uint32_t Af[4][4], B1[2][4], B2[2][4];
                #pragma unroll
                for (int m=0;m<4;m++) ldsm4(Af[m], st + bA[m] + ko);
                #pragma unroll
                for (int g=0;g<2;g++){ ldsm4(B1[g], st + bB[g] + ko); ldsm4(B2[g], st + bB[g] + 8192 + ko); }
                #pragma unroll
                for (int m=0;m<4;m++)
                    #pragma unroll
                    for (int nf=0;nf<4;nf++){
                        int g=nf>>1,o=nf&1;
                        mma16816(accT1[m][nf],Af[m],B1[g][o],B1[g][2+o]);
                        mma16816(accT2[m][nf],Af[m],B2[g][o],B2[g][2+o]);
                    }
            }
        }
    }
#undef LDQ

    #pragma unroll
    for (int m=0;m<4;m++)
        #pragma unroll
        for (int nf=0;nf<4;nf++)
            #pragma unroll
            for (int q=0;q<4;q++)
                accM[m][nf][q] += ampv[m][q>>1]*accT1[m][nf][q] + attv[m][q>>1]*accT2[m][nf][q];

    __syncthreads();
    float* redS=(float*)smem;
    if (tid<256) redS[tid]=0.f;
    __syncthreads();

    #pragma unroll
    for (int m=0;m<4;m++)
        #pragma unroll
        for (int nf=0;nf<4;nf++){
            int gm=m0+wm+m*16+lq;
            int gn=wn+nf*8+lrm*2;
            float b0=g_bias2[gn], b1=g_bias2[gn+1];
            float s0=0.f,q0=0.f,s1=0.f,q1=0.f;
            float* a4=accM[m][nf];
            #pragma unroll
            for (int hr=0;hr<2;hr++){
                int r=gm+hr*8;
                if (r<Nn){
                    float v0=a4[hr*2+0]+b0, v1=a4[hr*2+1]+b1;
                    __half2 p=__floats2half2_rn(v0,v1);
                    *(uint32_t*)(g_Yh+(size_t)r*128+gn)=*(uint32_t*)&p;
                    s0+=v0; q0+=v0*v0; s1+=v1; q1+=v1*v1;
                }
            }
            atomicAdd(&redS[gn], s0);    atomicAdd(&redS[128+gn], q0);
            atomicAdd(&redS[gn+1], s1);  atomicAdd(&redS[128+gn+1], q1);
        }
    __syncthreads();
    if (tid<128){ atomicAdd(&g_bnsum[tid], redS[tid]); atomicAdd(&g_bnsq[tid], redS[128+tid]); }
}

// ---------- tensor-core attention ----------
__global__ void __launch_bounds__(128) k_attn(const h16* __restrict__ qkv){
    __shared__ h16 qs[64*40], ks[64*40], vs[64*40];
    int bh=blockIdx.x, b=bh>>3, h=bh&7;
    int tid=threadIdx.x, lane=tid&31, wid=tid>>5;
    const h16* base = qkv + (size_t)b*64*768 + h*32;
    for (int i=tid;i<256;i+=128){
        int r=i>>2, c=(i&3)*8;
        *(uint4*)(qs+r*40+c)=*(const uint4*)(base+(size_t)r*768+c);
        *(uint4*)(ks+r*40+c)=*(const uint4*)(base+(size_t)r*768+256+c);
        *(uint4*)(vs+r*40+c)=*(const uint4*)(base+(size_t)r*768+512+c);
    }
    __syncthreads();
    uint32_t qb=smem_u32(qs), kb=smem_u32(ks), vb=smem_u32(vs);
    int m0=wid*16;
    float s[8][4];
    #pragma unroll
    for (int nt=0;nt<8;nt++)
        #pragma unroll
        for (int q=0;q<4;q++) s[nt][q]=0.f;

    #pragma unroll
    for (int kc=0;kc<2;kc++){
        uint32_t a[4];
        ldsm4(a, qb + (uint32_t)(m0+(lane&15))*80 + (uint32_t)((lane>>4)*8 + kc*16)*2);
        #pragma unroll
        for (int p=0;p<4;p++){
            uint32_t bf[4];
            ldsm4(bf, kb + (uint32_t)(p*16 + ((lane>>4)&1)*8 + (lane&7))*80
                        + (uint32_t)(kc*16 + ((lane>>3)&1)*8)*2);
            mma16816(s[2*p],  a, bf[0], bf[1]);
            mma16816(s[2*p+1],a, bf[2], bf[3]);
        }
    }

    const float scale=0.17677669529663687f;
    float mx1=-3.4e38f, mx2=-3.4e38f;
    #pragma unroll
    for (int nt=0;nt<8;nt++){
        mx1=fmaxf(mx1,fmaxf(s[nt][0],s[nt][1]));
        mx2=fmaxf(mx2,fmaxf(s[nt][2],s[nt][3]));
    }
    mx1=fmaxf(mx1,__shfl_xor_sync(~0u,mx1,1)); mx1=fmaxf(mx1,__shfl_xor_sync(~0u,mx1,2));
    mx2=fmaxf(mx2,__shfl_xor_sync(~0u,mx2,1)); mx2=fmaxf(mx2,__shfl_xor_sync(~0u,mx2,2));
    float sm1=0.f, sm2=0.f;
    #pragma unroll
    for (int nt=0;nt<8;nt++){
        s[nt][0]=__expf((s[nt][0]-mx1)*scale); s[nt][1]=__expf((s[nt][1]-mx1)*scale);
        s[nt][2]=__expf((s[nt][2]-mx2)*scale); s[nt][3]=__expf((s[nt][3]-mx2)*scale);
        sm1+=s[nt][0]+s[nt][1]; sm2+=s[nt][2]+s[nt][3];
    }
    sm1+=__shfl_xor_sync(~0u,sm1,1); sm1+=__shfl_xor_sync(~0u,sm1,2);
    sm2+=__shfl_xor_sync(~0u,sm2,1); sm2+=__shfl_xor_sync(~0u,sm2,2);
    float i1=1.f/sm1, i2=1.f/sm2;
    uint32_t ph1[8], ph2[8];
    #pragma unroll
    for (int nt=0;nt<8;nt++){
        __half2 t1=__floats2half2_rn(s[nt][0]*i1, s[nt][1]*i1);
        __half2 t2=__floats2half2_rn(s[nt][2]*i2, s[nt][3]*i2);
        ph1[nt]=*(uint32_t*)&t1; ph2[nt]=*(uint32_t*)&t2;
    }

    float o[4][4];
    #pragma unroll
    for (int nv=0;nv<4;nv++)
        #pragma unroll
        for (int q=0;q<4;q++) o[nv][q]=0.f;
    #pragma unroll
    for (int kc2=0;kc2<4;kc2++){
        uint32_t a[4]={ph1[2*kc2], ph2[2*kc2], ph1[2*kc2+1], ph2[2*kc2+1]};
        #pragma unroll
        for (int p=0;p<2;p++){
            uint32_t bf[4];
            ldsm4t(bf, vb + (uint32_t)(kc2*16 + ((lane>>3)&1)*8 + (lane&7))*80
                         + (uint32_t)((2*p + (lane>>4))*8)*2);
            mma16816(o[2*p],  a, bf[0], bf[1]);
            mma16816(o[2*p+1],a, bf[2], bf[3]);
        }
    }

    int lq=lane>>2, lrm=lane&3;
    int r1=b*64 + m0 + lq;
    #pragma unroll
    for (int nv=0;nv<4;nv++){
        int col=h*32 + nv*8 + lrm*2;
        __half2 t1=__floats2half2_rn(o[nv][0],o[nv][1]);
        __half2 t2=__floats2half2_rn(o[nv][2],o[nv][3]);
        *(uint32_t*)(g_aoh + (size_t)r1*256 + col)     = *(uint32_t*)&t1;
        *(uint32_t*)(g_aoh + (size_t)(r1+8)*256 + col) = *(uint32_t*)&t2;
    }
}

// ---------- prep (round-15 versions) ----------
__global__ void k_prep_pre(const float* __restrict__ pre_w, const float* __restrict__ pre_b,
                           const float* __restrict__ enc_w, const float* __restrict__ enc_b){
    int i=blockIdx.x, k=threadIdx.x;
    float v;
    if (k<256) v=pre_w[i*384+k];
    else { v=0.f; int kk=k-256; for (int j=0;j<128;j++) v+=pre_w[i*384+256+j]*enc_w[j*128+kk]; }
    h16 hv=__float2half(v);
    if (k<128)       g_wnode[i*128+k]=hv;
    else if (k<256)  g_wnode[(128+i)*128+(k-128)]=hv;
    else             g_wedge[i*128+(k-256)]=hv;
    if (k==0){ float t=pre_b[i]; for (int j=0;j<128;j++) t+=pre_w[i*384+256+j]*enc_b[j]; g_bpre[i]=t; }
}
// grid 385: blocks 0..383 build wstk; block 384 builds bias2
__global__ void k_prep_post(const float* __restrict__ linp_w, const float* __restrict__ post_w,
                            const float* __restrict__ post_b, const float* __restrict__ linp_b){
    int n=blockIdx.x, k=threadIdx.x;
    if (n==384){
        if (k<128){
            float t=linp_b[k];
            for (int j=0;j<128;j++) t+=linp_w[k*128+j]*post_b[j];
            g_bias2[k]=t;
        }
        return;
    }
    int s=n>>7, m=n&127;
    float v=0.f;
    if (k<128){ if (s==0){ for (int j=0;j<128;j++) v+=linp_w[m*128+j]*post_w[(size_t)j*1664+k]; } }
    else { int col=128+s*512+(k-128); for (int j=0;j<128;j++) v+=linp_w[m*128+j]*post_w[(size_t)j*1664+col]; }
    g_wstk_h[n*640+k]=__float2half(v);
}

// ---------- CSR ----------
__global__ void k_deg(const int* __restrict__ ei){
    int e=blockIdx.x*blockDim.x+threadIdx.x;
    if (e<Ee) atomicAdd(&g_deg[ei[Ee+e]],1);
}
__global__ void __launch_bounds__(1024) k_scan(){
    __shared__ int part[1024];
    int tid=threadIdx.x; const int chunk=(Nn+1023)/1024;
    int beg=tid*chunk, end=min(beg+chunk,Nn);
    int s=0; for (int i=beg;i<end;i++) s+=g_deg[i];
    part[tid]=s; __syncthreads();
    for (int d=1;d<1024;d<<=1){ int v=part[tid]; if (tid>=d) v+=part[tid-d]; __syncthreads(); part[tid]=v; __syncthreads(); }
    int off=(tid==0)?0:part[tid-1];
    for (int i=beg;i<end;i++){ g_rowstart[i]=off; off+=g_deg[i]; }
    if (end==Nn) g_rowstart[Nn]=off;
}
__global__ void k_scatter(const int* __restrict__ ei){
    int e=blockIdx.x*blockDim.x+threadIdx.x;
    if (e<Ee){ int d=ei[Ee+e]; int p=atomicAdd(&g_cursor[d],1); g_eid[g_rowstart[d]+p]=e; }
}

// ---------- aggregation: warp-per-node, contiguous rows, P1-shift applied ----------
__global__ void __launch_bounds__(128) k_agg(float delta){
    int w=threadIdx.x>>5, lane=threadIdx.x&31;
    int n=blockIdx.x*4+w;
    if (n>=Nn) return;
    int s=g_rowstart[n], e=g_rowstart[n+1];
    int c4=lane*4;
    float su[4]={0,0,0,0}, sq[4]={0,0,0,0};
    float mx[4], mn[4];
    #pragma unroll
    for (int i=0;i<4;i++){ mx[i]=-3.402823466e38f; mn[i]=3.402823466e38f; }
    for (int j=s;j<e;j++){
        uint2 v=*(const uint2*)(g_Hh+(size_t)j*128+c4);
        __half2 h0=*(__half2*)&v.x, h1=*(__half2*)&v.y;
        float f[4]={__low2float(h0),__high2float(h0),__low2float(h1),__high2float(h1)};
        #pragma unroll
        for (int i=0;i<4;i++){ su[i]+=f[i]; sq[i]+=f[i]*f[i]; mx[i]=fmaxf(mx[i],f[i]); mn[i]=fminf(mn[i],f[i]); }
    }
    float cnt=(float)(e-s), den=fmaxf(cnt,1.f);
    uint2 up=*(const uint2*)(g_p12+(size_t)n*256+c4);
    __half2 q0=*(__half2*)&up.x, q1=*(__half2*)&up.y;
    float pf[4]={__low2float(q0),__high2float(q0),__low2float(q1),__high2float(q1)};
    float mean[4], sd[4];
    #pragma unroll
    for (int i=0;i<4;i++){
        mean[i]=su[i]/den;
        sd[i]=sqrtf(fmaxf(sq[i]/den-mean[i]*mean[i],0.f)+EPSf);
        if (cnt<=0.f){ mx[i]=0.f; mn[i]=0.f; }
        else { mean[i]+=pf[i]; mx[i]+=pf[i]; mn[i]+=pf[i]; }
    }
    size_t b6=(size_t)n*640;
    *(uint2*)(g_aggh+b6+c4)=*(const uint2*)(g_xgh+(size_t)n*128+c4);
    __half2 a0,a1;
    a0=__floats2half2_rn(mean[0],mean[1]); a1=__floats2half2_rn(mean[2],mean[3]);
    { uint2 u; u.x=*(uint32_t*)&a0; u.y=*(uint32_t*)&a1; *(uint2*)(g_aggh+b6+128+c4)=u; }
    a0=__floats2half2_rn(mx[0],mx[1]); a1=__floats2half2_rn(mx[2],mx[3]);
    { uint2 u; u.x=*(uint32_t*)&a0; u.y=*(uint32_t*)&a1; *(uint2*)(g_aggh+b6+256+c4)=u; }
    a0=__floats2half2_rn(mn[0],mn[1]); a1=__floats2half2_rn(mn[2],mn[3]);
    { uint2 u; u.x=*(uint32_t*)&a0; u.y=*(uint32_t*)&a1; *(uint2*)(g_aggh+b6+384+c4)=u; }
    a0=__floats2half2_rn(sd[0],sd[1]); a1=__floats2half2_rn(sd[2],sd[3]);
    { uint2 u; u.x=*(uint32_t*)&a0; u.y=*(uint32_t*)&a1; *(uint2*)(g_aggh+b6+512+c4)=u; }
    if (lane==0){ float dc=fmaxf(cnt,1.f), lg=logf(dc+1.f); g_amp[n]=lg/delta; g_att[n]=delta/lg; }
}

// ---------- final (fp16 Y, fp32 x — round-15 numerics) ----------
__global__ void k_final(const float* __restrict__ xg, const float* __restrict__ bg,
                        const float* __restrict__ bb, float* __restrict__ out){
    int i=blockIdx.x*blockDim.x+threadIdx.x;
    if (i<Nn*128){
        int c=i&127;
        float mu=g_bnsum[c]*(1.f/Nn);
        float var=g_bnsq[c]*(1.f/Nn)-mu*mu;
        float y=bg[c]*(__half2float(g_Yh[i])-mu)*rsqrtf(var+EPSf)+bb[c];
        out[i]=(xg[i]+fmaxf(y,0.f))*0.5f;
    }
}

// ---------- launch ----------
extern "C" void kernel_launch(void* const* d_in, const int* in_sizes, int n_in,
                              void* d_out, int out_size)
{
    const float* x_tab=(const float*)d_in[0];
    const float* x_gnn=(const float*)d_in[1];
    const int*   ei   =(const int*)  d_in[2];
    const float* ea   =(const float*)d_in[3];
    const float* ipw=(const float*)d_in[4];  const float* ipb=(const float*)d_in[5];
    const float* opw=(const float*)d_in[6];  const float* opb=(const float*)d_in[7];
    const float* l1w=(const float*)d_in[8];  const float* l1b=(const float*)d_in[9];
    const float* l2w=(const float*)d_in[10]; const float* l2b=(const float*)d_in[11];
    const float* n1g=(const float*)d_in[12]; const float* n1b=(const float*)d_in[13];
    const float* n2g=(const float*)d_in[14]; const float* n2b=(const float*)d_in[15];
    const float* tng=(const float*)d_in[16]; const float* tnb=(const float*)d_in[17];
    const float* encw=(const float*)d_in[18];const float* encb=(const float*)d_in[19];
    const float* prew=(const float*)d_in[20];const float* preb=(const float*)d_in[21];
    const float* postw=(const float*)d_in[22];const float* postb=(const float*)d_in[23];
    const float* lpw=(const float*)d_in[24]; const float* lpb=(const float*)d_in[25];
    const float* bng=(const float*)d_in[26]; const float* bnb=(const float*)d_in[27];

    float* out_tab=(float*)d_out;
    float* out_gnn=(float*)d_out+TAB_OUT;
    float* out_ea =(float*)d_out+TAB_OUT+GNN_OUT;

    cudaFuncSetAttribute(k_mm<1>,  cudaFuncAttributeMaxDynamicSharedMemorySize, GEMM_SMEM);
    cudaFuncSetAttribute(k_mm<2>,  cudaFuncAttributeMaxDynamicSharedMemorySize, GEMM_SMEM);
    cudaFuncSetAttribute(k_mmln<1>, cudaFuncAttributeMaxDynamicSharedMemorySize, FSM);
    cudaFuncSetAttribute(k_mmln<2>, cudaFuncAttributeMaxDynamicSharedMemorySize, FSM);
    cudaFuncSetAttribute(k_mm_pre2, cudaFuncAttributeMaxDynamicSharedMemorySize, PRE_SMEM);
    cudaFuncSetAttribute(k_post3,  cudaFuncAttributeMaxDynamicSharedMemorySize, POST_SMEM);

    #define SYM(p,s) void* p; cudaGetSymbolAddress(&p, s)
    SYM(qkvh,g_qkvh); SYM(xth,g_xth); SYM(aoh,g_aoh);
    SYM(h1h,g_h1h); SYM(f1h,g_f1h);
    SYM(wqh,g_wq_h); SYM(woh,g_wo_h); SYM(w1h,g_w1_h); SYM(w2h,g_w2_h);
    SYM(xgh,g_xgh); SYM(eah,g_eah); SYM(p12,g_p12);
    SYM(wnode,g_wnode); SYM(bz,g_bz);

    const double dhh[5]={0.0,20000.0,30000.0,30000.0,20000.0};
    double sa=0.0,ta=0.0;
    for (int i=0;i<5;i++){ sa+=log((double)i+1.0)*dhh[i]; ta+=dhh[i]; }
    float delta=(float)(sa/ta);

    // one extra stream + two events (proven leak-free structure)
    cudaStream_t s1;
    cudaStreamCreateWithFlags(&s1, cudaStreamNonBlocking);
    cudaEvent_t ev0, ev1;
    cudaEventCreateWithFlags(&ev0, cudaEventDisableTiming);
    cudaEventCreateWithFlags(&ev1, cudaEventDisableTiming);
    cudaEventRecord(ev0, 0);
    cudaStreamWaitEvent(s1, ev0, 0);

    // ======== GNN branch on s1 ========
    k_zero<<<CDIV(Nn,256),256,0,s1>>>();
    k_r16<<<2048,256,0,s1>>>(x_gnn,(h16*)xgh,(size_t)Nn*128);
    k_ea16<<<4096,256,0,s1>>>((const float4*)ea,(float4*)out_ea,(uint2*)eah,(Ee*128)/4);
    k_prep_pre<<<128,384,0,s1>>>(prew,preb,encw,encb);
    k_prep_post<<<385,640,0,s1>>>(lpw,postw,postb,lpb);
    k_deg<<<CDIV(Ee,256),256,0,s1>>>(ei);
    k_scan<<<1,1024,0,s1>>>();
    k_scatter<<<CDIV(Ee,256),256,0,s1>>>(ei);
    k_mm<2><<<dim3(2,CDIV(Nn,128)),256,GEMM_SMEM,s1>>>((h16*)xgh,(h16*)wnode,(float*)bz,(h16*)p12,Nn,256,128);
    k_mm_pre2<<<Ee/128,256,PRE_SMEM,s1>>>(ei);
    k_agg<<<CDIV(Nn,4),128,0,s1>>>(delta);
    k_post3<<<CDIV(Nn,128),256,POST_SMEM,s1>>>();
    k_final<<<CDIV(Nn*128,256),256,0,s1>>>(x_gnn,bng,bnb,out_gnn);
    cudaEventRecord(ev1, s1);

    // ======== tab branch on default stream ========
    k_r16<<<2048,256>>>(x_tab,(h16*)xth,(size_t)RT*256);
    k_wconv<<<1024,256>>>(ipw,opw,l1w,l2w);
    k_mm<2><<<dim3(6,512),256,GEMM_SMEM>>>((h16*)xth,(h16*)wqh,ipb,(h16*)qkvh,RT,768,256);
    k_attn<<<8192,128>>>((h16*)qkvh);
    k_mmln<1><<<512,512,FSM>>>((h16*)aoh,(h16*)woh,opb,(h16*)xth,n1g,n1b,0,0,0,256);
    k_mm<1><<<dim3(8,512),256,GEMM_SMEM>>>((h16*)h1h,(h16*)w1h,l1b,(h16*)f1h,RT,1024,256);
    k_mmln<2><<<512,512,FSM>>>((h16*)f1h,(h16*)w2h,l2b,(h16*)h1h,n2g,n2b,tng,tnb,out_tab,1024);

    cudaStreamWaitEvent((cudaStream_t)0, ev1, 0);
}